// round 8
// baseline (speedup 1.0000x reference)
#include <cuda_runtime.h>
#include <cstdint>

// Problem constants (fixed by the reference setup_inputs)
#define TOKENS   4096
#define IN_F     8192
#define OUT_F    8192
#define NGROUPS  (IN_F / 64)      // 128 scale groups per output row
#define OCHUNKS  256              // o-reduction split
#define O_PER_CHUNK (OUT_F / OCHUNKS)  // 32
#define TILE_I   1024             // columns per block
#define GRPS_PER_TILE (TILE_I / 64)    // 16

// Scratch (allocation-free rule: __device__ globals)
__device__ float g_partial[OCHUNKS * IN_F];   // 8 MB partial v sums
__device__ float g_v[IN_F];                   // final v vector

__constant__ float c_nf4[16] = {
    -1.0f, -0.6961928009986877f, -0.5250730514526367f, -0.39491748809814453f,
    -0.28444138169288635f, -0.18477343022823334f, -0.09105003625154495f, 0.0f,
    0.07958029955625534f, 0.16093020141124725f, 0.24611230194568634f,
    0.33791524171829224f, 0.44070982933044434f, 0.5626170039176941f,
    0.7229568362236023f, 1.0f
};

// ---------------------------------------------------------------------------
// Kernel 1: partial[oc][i] = sum_{o in chunk oc} NF4[codes[o,i]]*scales[o,i/64]*w2[o]
// One int4 of codes per thread per o. Grid: (8, 256) = 2048 blocks, block 256
// -> 16384 warps: fills every warp slot on the chip (~100% occupancy).
// ---------------------------------------------------------------------------
__global__ void __launch_bounds__(256) k_dequant_reduce(
    const int*   __restrict__ codes,   // [OUT_F, IN_F]
    const float* __restrict__ scales,  // [OUT_F, NGROUPS]
    const float* __restrict__ w2)      // [OUT_F]
{
    // Bank-conflict-free NF4 table: tbl[c*32 + lane] == NF4[c].
    __shared__ float tbl[16 * 32];
    // s_tab[o][g] = w2[o0+o] * scales[o0+o, gbase+g]  (32 x 16 = 2 KB)
    __shared__ float s_tab[O_PER_CHUNK * GRPS_PER_TILE];

    const int tid = threadIdx.x;
    for (int idx = tid; idx < 16 * 32; idx += 256)
        tbl[idx] = c_nf4[idx >> 5];

    const int oc    = blockIdx.y;
    const int o0    = oc * O_PER_CHUNK;
    const int gbase = blockIdx.x * GRPS_PER_TILE;

    // Cooperative fill of s_tab: 512 entries, 2 per thread.
#pragma unroll
    for (int k = 0; k < 2; ++k) {
        int idx = tid + k * 256;
        int o = idx >> 4;            // 0..31
        int g = idx & 15;            // 0..15
        s_tab[idx] = __ldg(&w2[o0 + o]) *
                     __ldg(&scales[(size_t)(o0 + o) * NGROUPS + gbase + g]);
    }
    __syncthreads();

    const int lane = tid & 31;
    const float* lt = &tbl[lane];                 // lt[c<<5] hits lane's own bank

    const int i  = blockIdx.x * TILE_I + tid * 4; // 4-column group
    const int g0 = tid >> 4;                      // local scale group (0..15)

    const int4* cptr = reinterpret_cast<const int4*>(codes) +
                       (((size_t)o0 * IN_F + i) >> 2);
    const size_t cstride = IN_F / 4;              // int4 stride per o

    float s0 = 0.f, s1 = 0.f, s2 = 0.f, s3 = 0.f;

#pragma unroll 8
    for (int o = 0; o < O_PER_CHUNK; ++o) {
        int4 c = __ldcs(cptr);                    // streaming, one-touch
        cptr += cstride;
        float s = s_tab[o * GRPS_PER_TILE + g0];  // broadcast LDS
        s0 += s * lt[c.x << 5];
        s1 += s * lt[c.y << 5];
        s2 += s * lt[c.z << 5];
        s3 += s * lt[c.w << 5];
    }

    *reinterpret_cast<float4*>(&g_partial[(size_t)oc * IN_F + i]) =
        make_float4(s0, s1, s2, s3);
}

// ---------------------------------------------------------------------------
// Kernel 1b: v[i] = sum_oc partial[oc][i]   (fixed-order, deterministic)
// ---------------------------------------------------------------------------
__global__ void __launch_bounds__(256) k_reduce_chunks()
{
    const int i = blockIdx.x * blockDim.x + threadIdx.x;
    float s = 0.f;
#pragma unroll 16
    for (int c = 0; c < OCHUNKS; ++c)
        s += g_partial[(size_t)c * IN_F + i];
    g_v[i] = s;
}

// ---------------------------------------------------------------------------
// Kernel 2: out[t] = dot(x[t,:], v). 4 tokens per block, processed in pairs:
// one g_v load (L1-resident after first token) feeds two x rows.
// Grid: 1024 blocks x 256 threads.
// ---------------------------------------------------------------------------
__global__ void __launch_bounds__(256) k_xv(
    const float* __restrict__ x,      // [TOKENS, IN_F]
    float*       __restrict__ out)    // [TOKENS]
{
    const int tid  = threadIdx.x;
    const int wid  = tid >> 5;
    const int lane = tid & 31;
    const float4* vr = reinterpret_cast<const float4*>(g_v);

    __shared__ float warp_sums[2][8][2];          // [pair][warp][token-in-pair]

    const int tbase = blockIdx.x * 4;

#pragma unroll
    for (int p = 0; p < 2; ++p) {
        const int t0 = tbase + p * 2;
        const float4* xr0 = reinterpret_cast<const float4*>(x + (size_t)t0 * IN_F);
        const float4* xr1 = reinterpret_cast<const float4*>(x + (size_t)(t0 + 1) * IN_F);

        float sum0 = 0.f, sum1 = 0.f;
#pragma unroll
        for (int k = 0; k < (IN_F / 4) / 256; ++k) {
            int j = tid + k * 256;
            float4 v = __ldg(&vr[j]);             // L1-resident (32 KB)
            float4 a = __ldcs(&xr0[j]);           // streamed, one-touch
            float4 b = __ldcs(&xr1[j]);
            sum0 += a.x * v.x + a.y * v.y + a.z * v.z + a.w * v.w;
            sum1 += b.x * v.x + b.y * v.y + b.z * v.z + b.w * v.w;
        }

        for (int off = 16; off > 0; off >>= 1) {
            sum0 += __shfl_down_sync(0xFFFFFFFFu, sum0, off);
            sum1 += __shfl_down_sync(0xFFFFFFFFu, sum1, off);
        }
        if (lane == 0) {
            warp_sums[p][wid][0] = sum0;
            warp_sums[p][wid][1] = sum1;
        }
        __syncthreads();

        if (wid == 0) {
            float v0 = (lane < 8) ? warp_sums[p][lane][0] : 0.f;
            float v1 = (lane < 8) ? warp_sums[p][lane][1] : 0.f;
            for (int off = 4; off > 0; off >>= 1) {
                v0 += __shfl_down_sync(0xFFFFFFFFu, v0, off);
                v1 += __shfl_down_sync(0xFFFFFFFFu, v1, off);
            }
            if (lane == 0) {
                out[t0]     = v0;
                out[t0 + 1] = v1;
            }
        }
    }
}

// ---------------------------------------------------------------------------
// Launch
// ---------------------------------------------------------------------------
extern "C" void kernel_launch(void* const* d_in, const int* in_sizes, int n_in,
                              void* d_out, int out_size)
{
    const float* x      = (const float*)d_in[0];   // [4096, 8192] f32
    const int*   codes  = (const int*)  d_in[1];   // [8192, 8192] i32 (0..15)
    const float* scales = (const float*)d_in[2];   // [8192, 128]  f32
    const float* w2     = (const float*)d_in[3];   // [1, 8192]    f32
    float*       out    = (float*)d_out;           // [4096, 1]    f32

    (void)in_sizes; (void)n_in; (void)out_size;

    dim3 g1(IN_F / TILE_I, OCHUNKS);               // (8, 256) = 2048 blocks
    k_dequant_reduce<<<g1, 256>>>(codes, scales, w2);
    k_reduce_chunks<<<IN_F / 256, 256>>>();        // 32 blocks
    k_xv<<<TOKENS / 4, 256>>>(x, out);             // 1024 blocks
}

// round 9
// speedup vs baseline: 1.1144x; 1.1144x over previous
#include <cuda_runtime.h>
#include <cstdint>

// Problem constants (fixed by the reference setup_inputs)
#define TOKENS   4096
#define IN_F     8192
#define OUT_F    8192
#define NGROUPS  (IN_F / 64)      // 128 scale groups per output row
#define OCHUNKS  256              // o-reduction split
#define O_PER_CHUNK (OUT_F / OCHUNKS)  // 32
#define TILE_I   2048             // columns per k1 block (2 x 1024 halves)
#define RSTAGE   8                // stage-A outputs (each sums OCHUNKS/RSTAGE)

// Scratch (allocation-free rule: __device__ globals)
__device__ float g_partial[OCHUNKS * IN_F];   // 8 MB partial v sums
__device__ float g_stage[RSTAGE * IN_F];      // 256 KB stage-A sums
__device__ float g_v[IN_F];                   // final v vector

__constant__ float c_nf4[16] = {
    -1.0f, -0.6961928009986877f, -0.5250730514526367f, -0.39491748809814453f,
    -0.28444138169288635f, -0.18477343022823334f, -0.09105003625154495f, 0.0f,
    0.07958029955625534f, 0.16093020141124725f, 0.24611230194568634f,
    0.33791524171829224f, 0.44070982933044434f, 0.5626170039176941f,
    0.7229568362236023f, 1.0f
};

// ---------------------------------------------------------------------------
// Kernel 1 (measured best config, round 7: 44.2us = 97% of traffic floor):
// partial[oc][i] = sum_{o in chunk oc} NF4[codes[o,i]]*scales[o,i/64]*w2[o]
// Each thread owns 8 columns: i0..i0+3 and i0+1024..i0+1027 (two int4/o).
// Grid: (IN_F/TILE_I, OCHUNKS) = (4, 256), block 256.
// ---------------------------------------------------------------------------
__global__ void __launch_bounds__(256) k_dequant_reduce(
    const int*   __restrict__ codes,   // [OUT_F, IN_F]
    const float* __restrict__ scales,  // [OUT_F, NGROUPS]
    const float* __restrict__ w2)      // [OUT_F]
{
    __shared__ float tbl[16 * 32];                // lane-replicated NF4 table
    __shared__ float s_tab[O_PER_CHUNK * 32];     // w2*scale, 32x32 = 4 KB

    const int tid = threadIdx.x;
    for (int idx = tid; idx < 16 * 32; idx += 256)
        tbl[idx] = c_nf4[idx >> 5];

    const int oc    = blockIdx.y;
    const int o0    = oc * O_PER_CHUNK;
    const int gbase = blockIdx.x * (TILE_I / 64);    // 32 groups per tile

#pragma unroll
    for (int k = 0; k < 4; ++k) {
        int idx = tid + k * 256;
        int o = idx >> 5;            // 0..31
        int g = idx & 31;            // 0..31
        s_tab[idx] = __ldg(&w2[o0 + o]) *
                     __ldg(&scales[(size_t)(o0 + o) * NGROUPS + gbase + g]);
    }
    __syncthreads();

    const int lane = tid & 31;
    const float* lt = &tbl[lane];                 // lt[c<<5]: own-bank hit

    const int i0 = blockIdx.x * TILE_I + tid * 4;
    const int i1 = i0 + 1024;
    const int g0 = tid >> 4;                      // 0..15
    const int g1 = g0 + 16;                       // 16..31

    const int4* p0 = reinterpret_cast<const int4*>(codes) +
                     (((size_t)o0 * IN_F + i0) >> 2);
    const int4* p1 = p0 + (1024 >> 2);
    const size_t cstride = IN_F / 4;

    float a0 = 0.f, a1 = 0.f, a2 = 0.f, a3 = 0.f;
    float b0 = 0.f, b1 = 0.f, b2 = 0.f, b3 = 0.f;

#pragma unroll 8
    for (int o = 0; o < O_PER_CHUNK; ++o) {
        int4 ca = __ldcs(p0);                     // streaming, one-touch
        int4 cb = __ldcs(p1);
        p0 += cstride;
        p1 += cstride;
        float sa = s_tab[o * 32 + g0];            // broadcast LDS
        float sb = s_tab[o * 32 + g1];
        a0 += sa * lt[ca.x << 5];
        a1 += sa * lt[ca.y << 5];
        a2 += sa * lt[ca.z << 5];
        a3 += sa * lt[ca.w << 5];
        b0 += sb * lt[cb.x << 5];
        b1 += sb * lt[cb.y << 5];
        b2 += sb * lt[cb.z << 5];
        b3 += sb * lt[cb.w << 5];
    }

    float* dst = &g_partial[(size_t)oc * IN_F];
    *reinterpret_cast<float4*>(&dst[i0]) = make_float4(a0, a1, a2, a3);
    *reinterpret_cast<float4*>(&dst[i1]) = make_float4(b0, b1, b2, b3);
}

// ---------------------------------------------------------------------------
// Reduce stage A: g_stage[cj][i] = sum of 32 chunks. Grid (32, 8) = 256 blocks
// (8x the parallelism of the old single-stage reduce). Coalesced in i.
// ---------------------------------------------------------------------------
__global__ void __launch_bounds__(256) k_reduce_a()
{
    const int i  = blockIdx.x * 256 + threadIdx.x;
    const int c0 = blockIdx.y * (OCHUNKS / RSTAGE);
    float s = 0.f;
#pragma unroll
    for (int c = 0; c < OCHUNKS / RSTAGE; ++c)
        s += g_partial[(size_t)(c0 + c) * IN_F + i];
    g_stage[(size_t)blockIdx.y * IN_F + i] = s;
}

// ---------------------------------------------------------------------------
// Reduce stage B: v[i] = sum of 8 stage values (fixed order, deterministic).
// ---------------------------------------------------------------------------
__global__ void __launch_bounds__(256) k_reduce_b()
{
    const int i = blockIdx.x * 256 + threadIdx.x;
    float s = 0.f;
#pragma unroll
    for (int c = 0; c < RSTAGE; ++c)
        s += g_stage[(size_t)c * IN_F + i];
    g_v[i] = s;
}

// ---------------------------------------------------------------------------
// Kernel 2: out[t] = dot(x[t,:], v). 2 tokens per block, single pass:
// one v load (L1-resident) feeds two x rows; 3 outstanding loads per iter.
// Grid: 2048 blocks x 256 threads.
// ---------------------------------------------------------------------------
__global__ void __launch_bounds__(256) k_xv(
    const float* __restrict__ x,      // [TOKENS, IN_F]
    float*       __restrict__ out)    // [TOKENS]
{
    const int tid  = threadIdx.x;
    const int wid  = tid >> 5;
    const int lane = tid & 31;
    const int t0   = blockIdx.x * 2;

    const float4* vr  = reinterpret_cast<const float4*>(g_v);
    const float4* xr0 = reinterpret_cast<const float4*>(x + (size_t)t0 * IN_F);
    const float4* xr1 = reinterpret_cast<const float4*>(x + (size_t)(t0 + 1) * IN_F);

    float sum0 = 0.f, sum1 = 0.f;
#pragma unroll
    for (int k = 0; k < (IN_F / 4) / 256; ++k) {
        int j = tid + k * 256;
        float4 v = __ldg(&vr[j]);                 // hot in L1 within launch
        float4 a = __ldcs(&xr0[j]);               // streamed, one-touch
        float4 b = __ldcs(&xr1[j]);
        sum0 += a.x * v.x + a.y * v.y + a.z * v.z + a.w * v.w;
        sum1 += b.x * v.x + b.y * v.y + b.z * v.z + b.w * v.w;
    }

    for (int off = 16; off > 0; off >>= 1) {
        sum0 += __shfl_down_sync(0xFFFFFFFFu, sum0, off);
        sum1 += __shfl_down_sync(0xFFFFFFFFu, sum1, off);
    }

    __shared__ float ws[8][2];
    if (lane == 0) { ws[wid][0] = sum0; ws[wid][1] = sum1; }
    __syncthreads();

    if (wid == 0) {
        float v0 = (lane < 8) ? ws[lane][0] : 0.f;
        float v1 = (lane < 8) ? ws[lane][1] : 0.f;
        for (int off = 4; off > 0; off >>= 1) {
            v0 += __shfl_down_sync(0xFFFFFFFFu, v0, off);
            v1 += __shfl_down_sync(0xFFFFFFFFu, v1, off);
        }
        if (lane == 0) {
            out[t0]     = v0;
            out[t0 + 1] = v1;
        }
    }
}

// ---------------------------------------------------------------------------
// Launch
// ---------------------------------------------------------------------------
extern "C" void kernel_launch(void* const* d_in, const int* in_sizes, int n_in,
                              void* d_out, int out_size)
{
    const float* x      = (const float*)d_in[0];   // [4096, 8192] f32
    const int*   codes  = (const int*)  d_in[1];   // [8192, 8192] i32 (0..15)
    const float* scales = (const float*)d_in[2];   // [8192, 128]  f32
    const float* w2     = (const float*)d_in[3];   // [1, 8192]    f32
    float*       out    = (float*)d_out;           // [4096, 1]    f32

    (void)in_sizes; (void)n_in; (void)out_size;

    dim3 g1(IN_F / TILE_I, OCHUNKS);               // (4, 256)
    k_dequant_reduce<<<g1, 256>>>(codes, scales, w2);
    dim3 gr(IN_F / 256, RSTAGE);                   // (32, 8) = 256 blocks
    k_reduce_a<<<gr, 256>>>();
    k_reduce_b<<<IN_F / 256, 256>>>();             // 32 blocks
    k_xv<<<TOKENS / 2, 256>>>(x, out);             // 2048 blocks
}